// round 17
// baseline (speedup 1.0000x reference)
#include <cuda_runtime.h>
#include <cuda_fp16.h>
#include <cstdint>

// Shapes fixed by the problem: M=1024, K=4096, N=4096, group size 128.
#define M_DIM 1024
#define K_DIM 4096
#define N_DIM 4096

// Scratch (__device__ global; cudaMalloc forbidden): x converted fp32 -> fp16.
__device__ __half g_X[(size_t)M_DIM * K_DIM];

// ===========================================================================
// helpers
// ===========================================================================
__device__ __forceinline__ uint32_t smem_u32(const void* p) {
    uint32_t a;
    asm("{ .reg .u64 t; cvta.to.shared.u64 t, %1; cvt.u32.u64 %0, t; }"
        : "=r"(a) : "l"(p));
    return a;
}
__device__ __forceinline__ void cp16(uint32_t dst, const void* src) {
    size_t g = __cvta_generic_to_global(src);
    asm volatile("cp.async.cg.shared.global [%0], [%1], 16;\n" :: "r"(dst), "l"(g));
}
__device__ __forceinline__ void ldm_x4(uint32_t* r, uint32_t addr) {
    asm volatile("ldmatrix.sync.aligned.m8n8.x4.shared.b16 {%0,%1,%2,%3}, [%4];"
                 : "=r"(r[0]), "=r"(r[1]), "=r"(r[2]), "=r"(r[3]) : "r"(addr));
}
__device__ __forceinline__ void mma16816(float* d, const uint32_t* a,
                                         uint32_t b0, uint32_t b1) {
    asm volatile("mma.sync.aligned.m16n8k16.row.col.f32.f16.f16.f32 "
                 "{%0,%1,%2,%3}, {%4,%5,%6,%7}, {%8,%9}, {%0,%1,%2,%3};"
                 : "+f"(d[0]), "+f"(d[1]), "+f"(d[2]), "+f"(d[3])
                 : "r"(a[0]), "r"(a[1]), "r"(a[2]), "r"(a[3]), "r"(b0), "r"(b1));
}

#define MBAR_INIT(addr, cnt) \
    asm volatile("mbarrier.init.shared.b64 [%0], %1;" :: "r"(addr), "r"(cnt) : "memory")
#define MBAR_ARRIVE(addr) \
    asm volatile("mbarrier.arrive.shared.b64 _, [%0];" :: "r"(addr) : "memory")
#define CPASYNC_MBAR_ARRIVE_NOINC(addr) \
    asm volatile("cp.async.mbarrier.arrive.noinc.shared.b64 [%0];" :: "r"(addr) : "memory")
#define MBAR_WAIT(addr, parity) do {                                              \
    uint32_t _m = (addr); uint32_t _p = (parity); uint32_t _d;                    \
    asm volatile("{\n\t.reg .pred p;\n\t"                                         \
        "mbarrier.try_wait.parity.shared.b64 p, [%1], %2, 0x989680;\n\t"          \
        "selp.b32 %0, 1, 0, p;\n\t}"                                              \
        : "=r"(_d) : "r"(_m), "r"(_p) : "memory");                                \
    if (!_d) {                                                                    \
        asm volatile("{\n\t.reg .pred P1;\n\t"                                    \
            "WL_%=:\n\t"                                                          \
            "mbarrier.try_wait.parity.shared.b64 P1, [%0], %1, 0x989680;\n\t"     \
            "@P1 bra.uni WD_%=;\n\t"                                              \
            "bra.uni WL_%=;\n\t"                                                  \
            "WD_%=:\n\t}"                                                         \
            :: "r"(_m), "r"(_p) : "memory");                                      \
    }                                                                             \
} while (0)

// ===========================================================================
// Kernel 0: x fp32 -> fp16 (lossless; harness upcasts fp16 inputs to fp32).
// ===========================================================================
__global__ void convert_x_kernel(const float* __restrict__ x, size_t n) {
    size_t i = ((size_t)blockIdx.x * blockDim.x + threadIdx.x) * 8;
    if (i >= n) return;
    float4 a = *(const float4*)&x[i];
    float4 b = *(const float4*)&x[i + 4];
    __half2 h0 = __floats2half2_rn(a.x, a.y);
    __half2 h1 = __floats2half2_rn(a.z, a.w);
    __half2 h2 = __floats2half2_rn(b.x, b.y);
    __half2 h3 = __floats2half2_rn(b.z, b.w);
    uint4 u;
    u.x = *(uint32_t*)&h0; u.y = *(uint32_t*)&h1;
    u.z = *(uint32_t*)&h2; u.w = *(uint32_t*)&h3;
    *(uint4*)&g_X[i] = u;
}

// ===========================================================================
// Kernel 1: Marlin-style fused GPTQ GEMM + bias.
//   B is staged in SMEM as RAW int4 words (8 KB/chunk, cp.async only);
//   consumers dequant straight into mma B fragments (magic fp16 trick),
//   no B STS, no B ldmatrix. 320 threads: warps 0-7 consumers (64x64 tiles),
//   warps 8-9 producers (pure cp.async A + qweight). 5-stage ring, mbarrier
//   handshake, no __syncthreads in the mainloop.
// ===========================================================================
#define BM 128
#define BN 256
#define BKC 64
#define STAGES 5
#define ASTG (BM * BKC * 2)        // 16 KB fp16 A tile
#define QSTG (8 * BN * 4)          // 8 KB raw qweight (8 kp-rows x 256 words)
#define STG  (ASTG + QSTG)         // 24 KB
#define SMEM_TOT (STAGES * STG)    // 120 KB
#define NCONS 256                   // consumer threads (8 warps)

__global__ __launch_bounds__(320, 1)
void gemm_fused_kernel(const int* __restrict__ qw,
                       const float* __restrict__ scales,
                       const int* __restrict__ qz,
                       const int* __restrict__ gidx,
                       const float* __restrict__ bias,
                       float* __restrict__ out,
                       int M, int N, int K) {
    extern __shared__ char sm[];
    __shared__ __align__(8) unsigned long long full_s[STAGES], empty_s[STAGES];

    const int tid  = threadIdx.x;
    const int lane = tid & 31;
    const int warp = tid >> 5;
    const int mb   = blockIdx.y * BM;
    const int nb   = blockIdx.x * BN;
    const uint32_t sbase = smem_u32(sm);
    uint32_t fullb[STAGES], emptyb[STAGES];
#pragma unroll
    for (int s = 0; s < STAGES; s++) {
        fullb[s]  = smem_u32(&full_s[s]);
        emptyb[s] = smem_u32(&empty_s[s]);
    }

    if (tid == 0) {
#pragma unroll
        for (int s = 0; s < STAGES; s++) {
            MBAR_INIT(fullb[s], 64);     // 64 producer cp.async-completion arrives
            MBAR_INIT(emptyb[s], NCONS); // 256 consumer arrives
        }
    }
    __syncthreads();

    const int NKC = K / BKC;            // 64 chunks; group changes every 2

    if (warp >= 8) {
        // ============ PRODUCER (64 threads): pure cp.async ============
        const int tp = tid - NCONS;     // 0..63
        int st = 0, ph = 1;             // first STAGES empty-waits pass
        for (int kc = 0; kc < NKC; kc++) {
            MBAR_WAIT(emptyb[st], ph);
            const uint32_t sa = sbase + st * STG;
            const uint32_t sq = sa + ASTG;
            const int k0 = kc * BKC;
            // A: 128 rows x 128B (swizzled), 1024 x 16B chunks
#pragma unroll
            for (int t = 0; t < 16; t++) {
                int idx = t * 64 + tp;
                int r = idx >> 3, c = idx & 7;
                cp16(sa + r * 128 + ((c ^ (r & 7)) * 16),
                     g_X + (size_t)(mb + r) * K + k0 + c * 8);
            }
            // qweight raw: 8 kp-rows x 256 words (1KB/row), 512 x 16B chunks
#pragma unroll
            for (int t = 0; t < 8; t++) {
                int idx = t * 64 + tp;
                int r = idx >> 6, c = idx & 63;
                cp16(sq + r * 1024 + c * 16,
                     qw + (size_t)(kc * 8 + r) * N + nb + c * 4);
            }
            CPASYNC_MBAR_ARRIVE_NOINC(fullb[st]);
            if (++st == STAGES) { st = 0; ph ^= 1; }
        }
        return;
    }

    // ================== CONSUMER (256 threads) =====================
    const int wm = (warp & 1) * 64;     // 2 warps along M
    const int wn = (warp >> 1) * 64;    // 4 warps along N
    const int l4 = lane >> 2;           // n-within-octet owner (B frag n=l/4)
    const int sh = (lane & 3) * 8;      // nibble-pair shift (B frag k=2(l%4))

    float acc[4][8][4];
#pragma unroll
    for (int i = 0; i < 4; i++)
#pragma unroll
        for (int j = 0; j < 8; j++)
#pragma unroll
            for (int c = 0; c < 4; c++) acc[i][j][c] = 0.0f;

    __half2 s2[8], of2[8];              // per n-octet scale / (1025+zero)

    int st = 0, ph = 0;
    for (int kc = 0; kc < NKC; kc++) {
        if ((kc & 1) == 0) {
            // refresh group quantities (GS=128 = 2 chunks); overlaps the wait
            int g = kc >> 1;
#pragma unroll
            for (int o = 0; o < 8; o++) {
                int n_o = nb + wn + o * 8 + l4;
                float sf = scales[(size_t)g * N + n_o];
                unsigned zw = (unsigned)qz[(size_t)g * (N >> 3) + (n_o >> 3)];
                int z = (int)((zw >> (l4 * 4)) & 15u);   // n_o & 7 == l4
                s2[o]  = __half2half2(__float2half(sf));
                of2[o] = __half2half2(__float2half((float)(1025 + z)));
            }
        }
        MBAR_WAIT(fullb[st], ph);
        const uint32_t sa = sbase + st * STG;
        const uint32_t* qrow = (const uint32_t*)(sm + st * STG + ASTG);
#pragma unroll
        for (int kk = 0; kk < 4; kk++) {
            uint32_t a[4][4];
#pragma unroll
            for (int mi = 0; mi < 4; mi++) {
                int row = wm + mi * 16 + (lane & 15);
                int c   = kk * 2 + (lane >> 4);
                ldm_x4(a[mi], sa + row * 128 + ((c ^ (row & 7)) * 16));
            }
#pragma unroll
            for (int o = 0; o < 8; o++) {
                // raw words: kp rows 2kk (k 0..7) and 2kk+1 (k 8..15)
                int widx = wn + o * 8 + l4;
                uint32_t q0 = qrow[(kk * 2) * 256 + widx] >> sh;
                uint32_t q1 = qrow[(kk * 2 + 1) * 256 + widx] >> sh;
                uint32_t hb0 = (q0 & 0xFu) | ((q0 & 0xF0u) << 12) | 0x64006400u;
                uint32_t hb1 = (q1 & 0xFu) | ((q1 & 0xF0u) << 12) | 0x64006400u;
                __half2 b0 = __hmul2(__hsub2(*(__half2*)&hb0, of2[o]), s2[o]);
                __half2 b1 = __hmul2(__hsub2(*(__half2*)&hb1, of2[o]), s2[o]);
                uint32_t rb0 = *(uint32_t*)&b0, rb1 = *(uint32_t*)&b1;
#pragma unroll
                for (int mi = 0; mi < 4; mi++)
                    mma16816(acc[mi][o], a[mi], rb0, rb1);
            }
        }
        MBAR_ARRIVE(emptyb[st]);
        if (++st == STAGES) { st = 0; ph ^= 1; }
    }

    // ---- epilogue: + bias, fp32 out ----
    const int gq = lane >> 2, tq = lane & 3;
#pragma unroll
    for (int mi = 0; mi < 4; mi++) {
        int row0 = mb + wm + mi * 16 + gq;
#pragma unroll
        for (int o = 0; o < 8; o++) {
            int col = nb + wn + o * 8 + tq * 2;
            float b0 = bias[col];
            float b1 = bias[col + 1];
            float2 v0 = make_float2(acc[mi][o][0] + b0, acc[mi][o][1] + b1);
            float2 v1 = make_float2(acc[mi][o][2] + b0, acc[mi][o][3] + b1);
            *(float2*)&out[(size_t)row0 * N + col]       = v0;
            *(float2*)&out[(size_t)(row0 + 8) * N + col] = v1;
        }
    }
}

// ===========================================================================
// Launch: inputs in metadata order: x, qweight, scales, qzeros, g_idx, bias
// (fp16 tensors arrive upcast to float32)
// ===========================================================================
extern "C" void kernel_launch(void* const* d_in, const int* in_sizes, int n_in,
                              void* d_out, int out_size) {
    const float* x       = (const float*)d_in[0];
    const int*   qweight = (const int*)d_in[1];
    const float* scales  = (const float*)d_in[2];
    const int*   qzeros  = (const int*)d_in[3];
    const int*   g_idx   = (const int*)d_in[4];
    const float* bias    = (const float*)d_in[5];
    float*       out     = (float*)d_out;
    (void)g_idx;

    const int K = in_sizes[4];          // g_idx length
    const int N = in_sizes[5];          // bias length
    const int M = in_sizes[0] / K;      // x is [M, K]

    // 0) x fp32 -> fp16
    size_t nx = (size_t)M * K;
    convert_x_kernel<<<(unsigned)((nx / 8 + 255) / 256), 256>>>(x, nx);

    // 1) Marlin-style fused dequant-in-consumer GEMM + bias (128 CTAs)
    static bool attr_set = false;
    if (!attr_set) {
        cudaFuncSetAttribute(gemm_fused_kernel,
                             cudaFuncAttributeMaxDynamicSharedMemorySize, SMEM_TOT);
        attr_set = true;
    }
    dim3 gg(N / BN, M / BM);
    gemm_fused_kernel<<<gg, 320, SMEM_TOT>>>(qweight, scales, qzeros, g_idx,
                                             bias, out, M, N, K);
}